// round 13
// baseline (speedup 1.0000x reference)
#include <cuda_runtime.h>
#include <cuda_fp16.h>
#include <cuda_bf16.h>

// RoIAlign: features [4,1024,64,64] f32, rois [2048,5] f32 -> out [2048,1024,7,7] f32
//
// prep_kernel (fused compaction+geometry): one thread per roi claims a slot
// in its batch via atomicAdd, hoists roi geometry, writes all 49 (roi,bin)
// entries: {smem site, output offset, 4 bilinear weights as half2 (zeroed if
// out of bounds)}. Main kernel: block = (batch, 8-ch chunk, slice), 512
// threads, 65KB fp16 channel-interleaved smem, 3 CTAs/SM (1536 thr/SM,
// 42 regs -- the 32-reg cap at 2x1024thr serialized the corner loads).
// Per entry (8 outputs): 1 LDG.128 (register-pipelined) + 4 LDS.128 +
// 16 HFMA2 + 8 F2F + 8 coalesced STG.32.

#define B_    4
#define C_    1024
#define H_    64
#define W_    64
#define N_    2048
#define BINS  49
#define SCALE 0.0625f

#define CH       8
#define PLANE4   65                         // uint4-site row stride
#define SMEM_BYTES (H_ * PLANE4 * 16)       // 66560 B
#define NTHREADS 512
#define WPB      (NTHREADS / 32)            // 16 warps
#define SLICES   2

__device__ int   g_roi_cnt[B_];
__device__ uint4 g_geom[B_][N_ * BINS];

__global__ void prep_kernel(const float* __restrict__ rois) {
    int n = blockIdx.x * 256 + threadIdx.x;
    if (n >= N_) return;

    const float* rp = rois + n * 5;
    int   b  = (int)rp[0];
    float x1 = rp[1] * SCALE;
    float y1 = rp[2] * SCALE;
    float x2 = rp[3] * SCALE;
    float y2 = rp[4] * SCALE;
    float bw = fmaxf(x2 - x1, 0.0f) * (1.0f / 6.0f);
    float bh = fmaxf(y2 - y1, 0.0f) * (1.0f / 6.0f);

    int slot = atomicAdd(&g_roi_cnt[b], 1);
    uint4* __restrict__ dst = &g_geom[b][slot * BINS];
    unsigned obase = (unsigned)(n * (C_ * BINS));

    #pragma unroll 7
    for (int bin = 0; bin < BINS; bin++) {
        float phf = (float)(bin / 7);
        float pwf = (float)(bin % 7);
        float h = y1 + phf * bh;
        float w = x1 + pwf * bw;

        float hstart = fminf(floorf(h), (float)(H_ - 2));
        float wstart = fminf(floorf(w), (float)(W_ - 2));
        float hr = h - hstart;
        float wr = w - wstart;
        bool valid = (h >= 0.0f) && (h < (float)H_) &&
                     (w >= 0.0f) && (w < (float)W_);
        int hs = min(max((int)hstart, 0), H_ - 2);
        int ws = min(max((int)wstart, 0), W_ - 2);

        float omh = 1.0f - hr, omw = 1.0f - wr;
        float wa = omh * omw;
        float wb = omh * wr;
        float wc = hr * omw;
        float wd = hr * wr;
        if (!valid) { wa = wb = wc = wd = 0.0f; }

        __half2 hab = __floats2half2_rn(wa, wb);
        __half2 hcd = __floats2half2_rn(wc, wd);

        uint4 e;
        e.x = (unsigned)(hs * PLANE4 + ws);
        e.y = obase + (unsigned)bin;
        e.z = *reinterpret_cast<unsigned*>(&hab);
        e.w = *reinterpret_cast<unsigned*>(&hcd);
        dst[bin] = e;
    }
}

__global__ __launch_bounds__(NTHREADS, 3)
void roialign_kernel(const float* __restrict__ features,
                     float* __restrict__ out) {
    extern __shared__ uint4 sm[];                 // [hs*65+ws] -> 8 fp16 ch

    const int b     = blockIdx.y;
    const int c0    = (blockIdx.x >> 1) * CH;
    const int slice = blockIdx.x & (SLICES - 1);

    // ---- Stage: 8 coalesced channel streams -> fp16 interleaved ----
    {
        const float* src = features + (size_t)(b * C_ + c0) * (H_ * W_);
        #pragma unroll
        for (int k = 0; k < (H_ * W_) / NTHREADS; k++) {
            int i = k * NTHREADS + threadIdx.x;
            int row = i >> 6;
            int col = i & 63;
            __half2 h01 = __floats2half2_rn(src[i],            src[1 * 4096 + i]);
            __half2 h23 = __floats2half2_rn(src[2 * 4096 + i], src[3 * 4096 + i]);
            __half2 h45 = __floats2half2_rn(src[4 * 4096 + i], src[5 * 4096 + i]);
            __half2 h67 = __floats2half2_rn(src[6 * 4096 + i], src[7 * 4096 + i]);
            uint4 v;
            v.x = *reinterpret_cast<unsigned*>(&h01);
            v.y = *reinterpret_cast<unsigned*>(&h23);
            v.z = *reinterpret_cast<unsigned*>(&h45);
            v.w = *reinterpret_cast<unsigned*>(&h67);
            sm[row * PLANE4 + col] = v;
        }
    }
    __syncthreads();

    const int E    = g_roi_cnt[b] * BINS;
    const int lane = threadIdx.x & 31;
    const int warp = threadIdx.x >> 5;            // 0..15

    const uint4* __restrict__ gt = g_geom[b];
    float* __restrict__ obase = out + (size_t)c0 * BINS;

    const int STRIDE = SLICES * WPB * 32;         // 1024 entries
    int base0 = (slice * WPB + warp) * 32;

    uint4 gnext = (base0 + lane < E) ? __ldg(&gt[base0 + lane])
                                     : make_uint4(0u, 0u, 0u, 0u);

    for (int base = base0; base < E; base += STRIDE) {
        uint4 g = gnext;
        int nx = base + STRIDE + lane;
        if (nx < E) gnext = __ldg(&gt[nx]);

        if (base + lane < E) {
            int s = (int)g.x;

            __half2 wab = *reinterpret_cast<__half2*>(&g.z);
            __half2 wcd = *reinterpret_cast<__half2*>(&g.w);
            __half2 waa = __half2half2(__low2half(wab));
            __half2 wbb = __half2half2(__high2half(wab));
            __half2 wcc = __half2half2(__low2half(wcd));
            __half2 wdd = __half2half2(__high2half(wcd));

            uint4 ul = sm[s];
            uint4 ur = sm[s + 1];
            uint4 dl = sm[s + PLANE4];
            uint4 dr = sm[s + PLANE4 + 1];

            float* o = obase + g.y;

            const unsigned* pul = &ul.x;
            const unsigned* pur = &ur.x;
            const unsigned* pdl = &dl.x;
            const unsigned* pdr = &dr.x;
            #pragma unroll
            for (int j = 0; j < 4; j++) {
                __half2 acc = __hmul2(*reinterpret_cast<const __half2*>(&pul[j]), waa);
                acc = __hfma2(*reinterpret_cast<const __half2*>(&pur[j]), wbb, acc);
                acc = __hfma2(*reinterpret_cast<const __half2*>(&pdl[j]), wcc, acc);
                acc = __hfma2(*reinterpret_cast<const __half2*>(&pdr[j]), wdd, acc);
                float2 f = __half22float2(acc);
                o[(2 * j)     * BINS] = f.x;
                o[(2 * j + 1) * BINS] = f.y;
            }
        }
    }
}

extern "C" void kernel_launch(void* const* d_in, const int* in_sizes, int n_in,
                              void* d_out, int out_size) {
    const float* features = (const float*)d_in[0];
    const float* rois     = (const float*)d_in[1];
    float* out            = (float*)d_out;

    cudaFuncSetAttribute(roialign_kernel,
                         cudaFuncAttributeMaxDynamicSharedMemorySize,
                         SMEM_BYTES);

    void* cnt_ptr = nullptr;
    cudaGetSymbolAddress(&cnt_ptr, g_roi_cnt);
    cudaMemsetAsync(cnt_ptr, 0, B_ * sizeof(int));

    prep_kernel<<<N_ / 256, 256>>>(rois);
    {
        dim3 g((C_ / CH) * SLICES, B_);
        roialign_kernel<<<g, NTHREADS, SMEM_BYTES>>>(features, out);
    }
}

// round 15
// speedup vs baseline: 1.0292x; 1.0292x over previous
#include <cuda_runtime.h>
#include <cuda_fp16.h>
#include <cuda_bf16.h>

// RoIAlign: features [4,1024,64,64] f32, rois [2048,5] f32 -> out [2048,1024,7,7] f32
//
// prep_kernel (fused compaction+geometry): one thread per roi claims a slot
// in its batch via atomicAdd, hoists roi geometry, writes all 49 (roi,bin)
// entries: {smem site, output offset, 4 bilinear weights as half2 (zeroed
// if out of bounds)}. Main kernel: block = (batch, 8-ch chunk, slice),
// 768 threads, 65KB fp16 channel-interleaved smem, 2 CTAs/SM (1536 thr/SM,
// 42 regs -- the validated R12 sweet spot: enough registers to overlap the
// 4 corner LDS.128s, enough warps to hide latency). Per entry (8 outputs):
// 1 LDG.128 (register-pipelined) + 4 LDS.128 + 16 HFMA2 + 8 F2F +
// 8 coalesced STG.32.

#define B_    4
#define C_    1024
#define H_    64
#define W_    64
#define N_    2048
#define BINS  49
#define SCALE 0.0625f

#define CH       8
#define PLANE4   65                         // uint4-site row stride
#define SMEM_BYTES (H_ * PLANE4 * 16)       // 66560 B
#define NTHREADS 768
#define WPB      (NTHREADS / 32)            // 24 warps
#define SLICES   2

__device__ int   g_roi_cnt[B_];
__device__ uint4 g_geom[B_][N_ * BINS];

__global__ void prep_kernel(const float* __restrict__ rois) {
    int n = blockIdx.x * 256 + threadIdx.x;
    if (n >= N_) return;

    const float* rp = rois + n * 5;
    int   b  = (int)rp[0];
    float x1 = rp[1] * SCALE;
    float y1 = rp[2] * SCALE;
    float x2 = rp[3] * SCALE;
    float y2 = rp[4] * SCALE;
    float bw = fmaxf(x2 - x1, 0.0f) * (1.0f / 6.0f);
    float bh = fmaxf(y2 - y1, 0.0f) * (1.0f / 6.0f);

    int slot = atomicAdd(&g_roi_cnt[b], 1);
    uint4* __restrict__ dst = &g_geom[b][slot * BINS];
    unsigned obase = (unsigned)(n * (C_ * BINS));

    #pragma unroll 7
    for (int bin = 0; bin < BINS; bin++) {
        float phf = (float)(bin / 7);
        float pwf = (float)(bin % 7);
        float h = y1 + phf * bh;
        float w = x1 + pwf * bw;

        float hstart = fminf(floorf(h), (float)(H_ - 2));
        float wstart = fminf(floorf(w), (float)(W_ - 2));
        float hr = h - hstart;
        float wr = w - wstart;
        bool valid = (h >= 0.0f) && (h < (float)H_) &&
                     (w >= 0.0f) && (w < (float)W_);
        int hs = min(max((int)hstart, 0), H_ - 2);
        int ws = min(max((int)wstart, 0), W_ - 2);

        float omh = 1.0f - hr, omw = 1.0f - wr;
        float wa = omh * omw;
        float wb = omh * wr;
        float wc = hr * omw;
        float wd = hr * wr;
        if (!valid) { wa = wb = wc = wd = 0.0f; }

        __half2 hab = __floats2half2_rn(wa, wb);
        __half2 hcd = __floats2half2_rn(wc, wd);

        uint4 e;
        e.x = (unsigned)(hs * PLANE4 + ws);
        e.y = obase + (unsigned)bin;
        e.z = *reinterpret_cast<unsigned*>(&hab);
        e.w = *reinterpret_cast<unsigned*>(&hcd);
        dst[bin] = e;
    }
}

__global__ __launch_bounds__(NTHREADS, 2)
void roialign_kernel(const float* __restrict__ features,
                     float* __restrict__ out) {
    extern __shared__ uint4 sm[];                 // [hs*65+ws] -> 8 fp16 ch

    const int b     = blockIdx.y;
    const int c0    = (blockIdx.x >> 1) * CH;
    const int slice = blockIdx.x & (SLICES - 1);

    // ---- Stage: 8 coalesced channel streams -> fp16 interleaved ----
    {
        const float* src = features + (size_t)(b * C_ + c0) * (H_ * W_);
        #pragma unroll
        for (int k = 0; k < 6; k++) {
            int i = k * NTHREADS + threadIdx.x;
            if (i < H_ * W_) {
                int row = i >> 6;
                int col = i & 63;
                __half2 h01 = __floats2half2_rn(src[i],            src[1 * 4096 + i]);
                __half2 h23 = __floats2half2_rn(src[2 * 4096 + i], src[3 * 4096 + i]);
                __half2 h45 = __floats2half2_rn(src[4 * 4096 + i], src[5 * 4096 + i]);
                __half2 h67 = __floats2half2_rn(src[6 * 4096 + i], src[7 * 4096 + i]);
                uint4 v;
                v.x = *reinterpret_cast<unsigned*>(&h01);
                v.y = *reinterpret_cast<unsigned*>(&h23);
                v.z = *reinterpret_cast<unsigned*>(&h45);
                v.w = *reinterpret_cast<unsigned*>(&h67);
                sm[row * PLANE4 + col] = v;
            }
        }
    }
    __syncthreads();

    const int E    = g_roi_cnt[b] * BINS;
    const int lane = threadIdx.x & 31;
    const int warp = threadIdx.x >> 5;            // 0..23

    const uint4* __restrict__ gt = g_geom[b];
    float* __restrict__ obase = out + (size_t)c0 * BINS;

    const int STRIDE = SLICES * WPB * 32;         // 1536 entries
    int base0 = (slice * WPB + warp) * 32;

    uint4 gnext = (base0 + lane < E) ? __ldg(&gt[base0 + lane])
                                     : make_uint4(0u, 0u, 0u, 0u);

    for (int base = base0; base < E; base += STRIDE) {
        uint4 g = gnext;
        int nx = base + STRIDE + lane;
        if (nx < E) gnext = __ldg(&gt[nx]);

        if (base + lane < E) {
            int s = (int)g.x;

            __half2 wab = *reinterpret_cast<__half2*>(&g.z);
            __half2 wcd = *reinterpret_cast<__half2*>(&g.w);
            __half2 waa = __half2half2(__low2half(wab));
            __half2 wbb = __half2half2(__high2half(wab));
            __half2 wcc = __half2half2(__low2half(wcd));
            __half2 wdd = __half2half2(__high2half(wcd));

            uint4 ul = sm[s];
            uint4 ur = sm[s + 1];
            uint4 dl = sm[s + PLANE4];
            uint4 dr = sm[s + PLANE4 + 1];

            float* o = obase + g.y;

            const unsigned* pul = &ul.x;
            const unsigned* pur = &ur.x;
            const unsigned* pdl = &dl.x;
            const unsigned* pdr = &dr.x;
            #pragma unroll
            for (int j = 0; j < 4; j++) {
                __half2 acc = __hmul2(*reinterpret_cast<const __half2*>(&pul[j]), waa);
                acc = __hfma2(*reinterpret_cast<const __half2*>(&pur[j]), wbb, acc);
                acc = __hfma2(*reinterpret_cast<const __half2*>(&pdl[j]), wcc, acc);
                acc = __hfma2(*reinterpret_cast<const __half2*>(&pdr[j]), wdd, acc);
                float2 f = __half22float2(acc);
                o[(2 * j)     * BINS] = f.x;
                o[(2 * j + 1) * BINS] = f.y;
            }
        }
    }
}

extern "C" void kernel_launch(void* const* d_in, const int* in_sizes, int n_in,
                              void* d_out, int out_size) {
    const float* features = (const float*)d_in[0];
    const float* rois     = (const float*)d_in[1];
    float* out            = (float*)d_out;

    cudaFuncSetAttribute(roialign_kernel,
                         cudaFuncAttributeMaxDynamicSharedMemorySize,
                         SMEM_BYTES);

    void* cnt_ptr = nullptr;
    cudaGetSymbolAddress(&cnt_ptr, g_roi_cnt);
    cudaMemsetAsync(cnt_ptr, 0, B_ * sizeof(int));

    prep_kernel<<<N_ / 256, 256>>>(rois);
    {
        dim3 g((C_ / CH) * SLICES, B_);
        roialign_kernel<<<g, NTHREADS, SMEM_BYTES>>>(features, out);
    }
}

// round 16
// speedup vs baseline: 1.0819x; 1.0512x over previous
#include <cuda_runtime.h>
#include <cuda_fp16.h>
#include <cuda_bf16.h>

// RoIAlign: features [4,1024,64,64] f32, rois [2048,5] f32 -> out [2048,1024,7,7] f32
//
// prep_kernel: WARP-per-roi (256 blocks x 256 thr -> 2048 warps). Lanes 0-4
// cooperatively load the roi row (shfl broadcast), lane0 claims the batch
// slot via atomicAdd, then all 32 lanes compute the 49 bins in parallel
// (bins lane, lane+32) and write contiguous uint4 entries:
// {smem site, output offset, 4 bilinear weights as half2 (zeroed if OOB)}.
// (R15's thread-per-roi prep ran on only 8 blocks -> ~8us serial tail.)
//
// Main kernel (byte-identical to validated R12/R15 config): block = (batch,
// 8-ch chunk, slice), 768 threads, 65KB fp16 channel-interleaved smem,
// 2 CTAs/SM, 38 regs. Per entry (8 outputs): 1 LDG.128 (register-pipelined)
// + 4 LDS.128 + 16 HFMA2 + 8 F2F + 8 coalesced STG.32.

#define B_    4
#define C_    1024
#define H_    64
#define W_    64
#define N_    2048
#define BINS  49
#define SCALE 0.0625f

#define CH       8
#define PLANE4   65                         // uint4-site row stride
#define SMEM_BYTES (H_ * PLANE4 * 16)       // 66560 B
#define NTHREADS 768
#define WPB      (NTHREADS / 32)            // 24 warps
#define SLICES   2

__device__ int   g_roi_cnt[B_];
__device__ uint4 g_geom[B_][N_ * BINS];

__global__ void prep_kernel(const float* __restrict__ rois) {
    const int lane = threadIdx.x & 31;
    const int warp = threadIdx.x >> 5;            // 0..7
    const int n    = blockIdx.x * 8 + warp;       // grid 256 * 8 = 2048 = N_

    float v = (lane < 5) ? __ldg(&rois[n * 5 + lane]) : 0.0f;
    int   b  = (int)__shfl_sync(0xffffffffu, v, 0);
    float x1 = __shfl_sync(0xffffffffu, v, 1) * SCALE;
    float y1 = __shfl_sync(0xffffffffu, v, 2) * SCALE;
    float x2 = __shfl_sync(0xffffffffu, v, 3) * SCALE;
    float y2 = __shfl_sync(0xffffffffu, v, 4) * SCALE;

    float bw = fmaxf(x2 - x1, 0.0f) * (1.0f / 6.0f);
    float bh = fmaxf(y2 - y1, 0.0f) * (1.0f / 6.0f);

    int slot = 0;
    if (lane == 0) slot = atomicAdd(&g_roi_cnt[b], 1);
    slot = __shfl_sync(0xffffffffu, slot, 0);

    uint4* __restrict__ dst = &g_geom[b][slot * BINS];
    unsigned obase = (unsigned)(n * (C_ * BINS));

    #pragma unroll
    for (int t = 0; t < 2; t++) {
        int bin = lane + t * 32;
        if (bin < BINS) {
            float phf = (float)(bin / 7);
            float pwf = (float)(bin % 7);
            float h = y1 + phf * bh;
            float w = x1 + pwf * bw;

            float hstart = fminf(floorf(h), (float)(H_ - 2));
            float wstart = fminf(floorf(w), (float)(W_ - 2));
            float hr = h - hstart;
            float wr = w - wstart;
            bool valid = (h >= 0.0f) && (h < (float)H_) &&
                         (w >= 0.0f) && (w < (float)W_);
            int hs = min(max((int)hstart, 0), H_ - 2);
            int ws = min(max((int)wstart, 0), W_ - 2);

            float omh = 1.0f - hr, omw = 1.0f - wr;
            float wa = omh * omw;
            float wb = omh * wr;
            float wc = hr * omw;
            float wd = hr * wr;
            if (!valid) { wa = wb = wc = wd = 0.0f; }

            __half2 hab = __floats2half2_rn(wa, wb);
            __half2 hcd = __floats2half2_rn(wc, wd);

            uint4 e;
            e.x = (unsigned)(hs * PLANE4 + ws);
            e.y = obase + (unsigned)bin;
            e.z = *reinterpret_cast<unsigned*>(&hab);
            e.w = *reinterpret_cast<unsigned*>(&hcd);
            dst[bin] = e;
        }
    }
}

__global__ __launch_bounds__(NTHREADS, 2)
void roialign_kernel(const float* __restrict__ features,
                     float* __restrict__ out) {
    extern __shared__ uint4 sm[];                 // [hs*65+ws] -> 8 fp16 ch

    const int b     = blockIdx.y;
    const int c0    = (blockIdx.x >> 1) * CH;
    const int slice = blockIdx.x & (SLICES - 1);

    // ---- Stage: 8 coalesced channel streams -> fp16 interleaved ----
    {
        const float* src = features + (size_t)(b * C_ + c0) * (H_ * W_);
        #pragma unroll
        for (int k = 0; k < 6; k++) {
            int i = k * NTHREADS + threadIdx.x;
            if (i < H_ * W_) {
                int row = i >> 6;
                int col = i & 63;
                __half2 h01 = __floats2half2_rn(src[i],            src[1 * 4096 + i]);
                __half2 h23 = __floats2half2_rn(src[2 * 4096 + i], src[3 * 4096 + i]);
                __half2 h45 = __floats2half2_rn(src[4 * 4096 + i], src[5 * 4096 + i]);
                __half2 h67 = __floats2half2_rn(src[6 * 4096 + i], src[7 * 4096 + i]);
                uint4 v;
                v.x = *reinterpret_cast<unsigned*>(&h01);
                v.y = *reinterpret_cast<unsigned*>(&h23);
                v.z = *reinterpret_cast<unsigned*>(&h45);
                v.w = *reinterpret_cast<unsigned*>(&h67);
                sm[row * PLANE4 + col] = v;
            }
        }
    }
    __syncthreads();

    const int E    = g_roi_cnt[b] * BINS;
    const int lane = threadIdx.x & 31;
    const int warp = threadIdx.x >> 5;            // 0..23

    const uint4* __restrict__ gt = g_geom[b];
    float* __restrict__ obase = out + (size_t)c0 * BINS;

    const int STRIDE = SLICES * WPB * 32;         // 1536 entries
    int base0 = (slice * WPB + warp) * 32;

    uint4 gnext = (base0 + lane < E) ? __ldg(&gt[base0 + lane])
                                     : make_uint4(0u, 0u, 0u, 0u);

    for (int base = base0; base < E; base += STRIDE) {
        uint4 g = gnext;
        int nx = base + STRIDE + lane;
        if (nx < E) gnext = __ldg(&gt[nx]);

        if (base + lane < E) {
            int s = (int)g.x;

            __half2 wab = *reinterpret_cast<__half2*>(&g.z);
            __half2 wcd = *reinterpret_cast<__half2*>(&g.w);
            __half2 waa = __half2half2(__low2half(wab));
            __half2 wbb = __half2half2(__high2half(wab));
            __half2 wcc = __half2half2(__low2half(wcd));
            __half2 wdd = __half2half2(__high2half(wcd));

            uint4 ul = sm[s];
            uint4 ur = sm[s + 1];
            uint4 dl = sm[s + PLANE4];
            uint4 dr = sm[s + PLANE4 + 1];

            float* o = obase + g.y;

            const unsigned* pul = &ul.x;
            const unsigned* pur = &ur.x;
            const unsigned* pdl = &dl.x;
            const unsigned* pdr = &dr.x;
            #pragma unroll
            for (int j = 0; j < 4; j++) {
                __half2 acc = __hmul2(*reinterpret_cast<const __half2*>(&pul[j]), waa);
                acc = __hfma2(*reinterpret_cast<const __half2*>(&pur[j]), wbb, acc);
                acc = __hfma2(*reinterpret_cast<const __half2*>(&pdl[j]), wcc, acc);
                acc = __hfma2(*reinterpret_cast<const __half2*>(&pdr[j]), wdd, acc);
                float2 f = __half22float2(acc);
                o[(2 * j)     * BINS] = f.x;
                o[(2 * j + 1) * BINS] = f.y;
            }
        }
    }
}

extern "C" void kernel_launch(void* const* d_in, const int* in_sizes, int n_in,
                              void* d_out, int out_size) {
    const float* features = (const float*)d_in[0];
    const float* rois     = (const float*)d_in[1];
    float* out            = (float*)d_out;

    cudaFuncSetAttribute(roialign_kernel,
                         cudaFuncAttributeMaxDynamicSharedMemorySize,
                         SMEM_BYTES);

    void* cnt_ptr = nullptr;
    cudaGetSymbolAddress(&cnt_ptr, g_roi_cnt);
    cudaMemsetAsync(cnt_ptr, 0, B_ * sizeof(int));

    prep_kernel<<<N_ / 8, 256>>>(rois);
    {
        dim3 g((C_ / CH) * SLICES, B_);
        roialign_kernel<<<g, NTHREADS, SMEM_BYTES>>>(features, out);
    }
}